// round 1
// baseline (speedup 1.0000x reference)
#include <cuda_runtime.h>
#include <math.h>

// Problem constants
#define Hd   512
#define G4   2048      // 4*H
#define Ed   250
#define Bd   32
#define NCd  5
#define Td   20
#define Rd   160       // NC*B
#define Vd   30522
#define CNNd 2048
#define Md   3200      // NC*T*B

// ---------------- device scratch (no allocations allowed) ----------------
// Packed weights: B-matrix layout [K][N], N interleaved as n = h*4 + gate
__device__ float g_WihP0[2][Ed][G4];
__device__ float g_WhhP0[2][Hd][G4];
__device__ float g_WihP1[2][2 * Hd][G4];
__device__ float g_WhhP1[2][Hd][G4];
__device__ float g_bP0[2][G4];
__device__ float g_bP1[2][G4];
// Precomputed layer0 input projections (prefix-invariant): [dir][t][row][n]
__device__ float g_X0[2][Td][Rd][G4];
// Per-w layer1 input projections: [dir][t][row][n]
__device__ float g_Z[2][Td][Rd][G4];
// LSTM h state, double buffered: [parity][layer][dir][row][h]
__device__ float g_hbuf[2][2][2][Rd][Hd];
// LSTM c state (in-place safe): [layer][dir][row][h]
__device__ float g_cS[2][2][Rd][Hd];
// layer0 output sequences (scan order): [dir][s][row][h]
__device__ float g_hs[2][Td][Rd][Hd];
// packed final states for vocab projection: [m][2H]
__device__ float g_packed[Md][2 * Hd];

// ---------------- weight packing ----------------
__global__ void k_pack(const float* __restrict__ Wih0, const float* __restrict__ Whh0,
                       const float* __restrict__ bih0, const float* __restrict__ bhh0,
                       const float* __restrict__ Wih1, const float* __restrict__ Whh1,
                       const float* __restrict__ bih1, const float* __restrict__ bhh1) {
    int region = blockIdx.y;
    long i = (long)blockIdx.x * blockDim.x + threadIdx.x;
    if (region == 0) {                       // WihP0: [2][250][2048]
        if (i >= 2L * Ed * G4) return;
        int d = (int)(i / (Ed * G4)); int rem = (int)(i % (Ed * G4));
        int k = rem / G4, n = rem % G4;
        int h = n >> 2, g = n & 3;
        g_WihP0[d][k][n] = Wih0[((long)d * G4 + g * Hd + h) * Ed + k];
    } else if (region == 1) {                // WhhP0: [2][512][2048]
        if (i >= 2L * Hd * G4) return;
        int d = (int)(i / (Hd * G4)); int rem = (int)(i % (Hd * G4));
        int k = rem / G4, n = rem % G4;
        int h = n >> 2, g = n & 3;
        g_WhhP0[d][k][n] = Whh0[((long)d * G4 + g * Hd + h) * Hd + k];
    } else if (region == 2) {                // WihP1: [2][1024][2048]
        if (i >= 2L * 2 * Hd * G4) return;
        int d = (int)(i / (2 * Hd * G4)); int rem = (int)(i % (2 * Hd * G4));
        int k = rem / G4, n = rem % G4;
        int h = n >> 2, g = n & 3;
        g_WihP1[d][k][n] = Wih1[((long)d * G4 + g * Hd + h) * (2 * Hd) + k];
    } else if (region == 3) {                // WhhP1: [2][512][2048]
        if (i >= 2L * Hd * G4) return;
        int d = (int)(i / (Hd * G4)); int rem = (int)(i % (Hd * G4));
        int k = rem / G4, n = rem % G4;
        int h = n >> 2, g = n & 3;
        g_WhhP1[d][k][n] = Whh1[((long)d * G4 + g * Hd + h) * Hd + k];
    } else if (region == 4) {                // bP0
        if (i >= 2L * G4) return;
        int d = (int)(i / G4); int n = (int)(i % G4);
        int h = n >> 2, g = n & 3;
        long j = (long)d * G4 + g * Hd + h;
        g_bP0[d][n] = bih0[j] + bhh0[j];
    } else {                                 // bP1
        if (i >= 2L * G4) return;
        int d = (int)(i / G4); int n = (int)(i % G4);
        int h = n >> 2, g = n & 3;
        long j = (long)d * G4 + g * Hd + h;
        g_bP1[d][n] = bih1[j] + bhh1[j];
    }
}

// ---------------- initial states: h0/c0 = relu(img @ W.T + b), broadcast ----------------
__global__ void k_init(const float* __restrict__ img, const float* __restrict__ Wh,
                       const float* __restrict__ bh, const float* __restrict__ Wc,
                       const float* __restrict__ bc) {
    int i = blockIdx.x * blockDim.x + threadIdx.x;    // 2 * 32 * 512
    if (i >= 2 * Bd * Hd) return;
    int which = i / (Bd * Hd);
    int rem = i % (Bd * Hd);
    int b = rem / Hd, j = rem % Hd;
    const float* W = which ? Wc : Wh;
    const float* bias = which ? bc : bh;
    const float4* a4 = (const float4*)(img + (long)b * CNNd);
    const float4* w4 = (const float4*)(W + (long)j * CNNd);
    float acc = 0.f;
#pragma unroll 4
    for (int k = 0; k < CNNd / 4; k++) {
        float4 a = a4[k], w = w4[k];
        acc += a.x * w.x + a.y * w.y + a.z * w.z + a.w * w.w;
    }
    float v = fmaxf(acc + bias[j], 0.f);
    for (int nc = 0; nc < NCd; nc++) {
        int row = nc * Bd + b;
        for (int l = 0; l < 2; l++)
            for (int d = 0; d < 2; d++) {
                if (which == 0) g_hbuf[0][l][d][row][j] = v;
                else            g_cS[l][d][row][j] = v;
            }
    }
}

// ---------------- layer0 input projections for all t (prefix-invariant) ----------------
// grid (100, 16, 2), block 256. C[m][n] = emb[tok(m)] @ WihP0[d] + bP0[d]
__global__ void k_xproj(const float* __restrict__ emb, const int* __restrict__ cap) {
    __shared__ float xs[32 * Ed];
    __shared__ int toks[32];
    int bm = blockIdx.x, bn = blockIdx.y, d = blockIdx.z;
    int tid = threadIdx.x;
    if (tid < 32) {
        int m = bm * 32 + tid;
        int t = m / Rd, r = m % Rd;
        int nc = r >> 5, b = r & 31;
        toks[tid] = cap[b * (NCd * Td) + nc * Td + t];
    }
    __syncthreads();
    for (int e = tid; e < 32 * Ed; e += 256) {
        int lr = e / Ed, k = e % Ed;
        xs[e] = emb[(long)toks[lr] * Ed + k];
    }
    __syncthreads();
    int tx = tid & 31, ty = tid >> 5;     // rows: ty + jr*8 ; cols: tx + jc*32
    float acc[4][4];
#pragma unroll
    for (int a = 0; a < 4; a++)
#pragma unroll
        for (int c = 0; c < 4; c++) acc[a][c] = 0.f;
    int n0 = bn * 128;
    const float* Bp = &g_WihP0[d][0][0];
#pragma unroll 2
    for (int k = 0; k < Ed; k++) {
        float av[4], bv[4];
#pragma unroll
        for (int jr = 0; jr < 4; jr++) av[jr] = xs[(ty + jr * 8) * Ed + k];
#pragma unroll
        for (int jc = 0; jc < 4; jc++) bv[jc] = Bp[(long)k * G4 + n0 + tx + jc * 32];
#pragma unroll
        for (int jr = 0; jr < 4; jr++)
#pragma unroll
            for (int jc = 0; jc < 4; jc++) acc[jr][jc] += av[jr] * bv[jc];
    }
    int m0 = bm * 32;
#pragma unroll
    for (int jr = 0; jr < 4; jr++) {
        int m = m0 + ty + jr * 8;
        int t = m / Rd, r = m % Rd;
#pragma unroll
        for (int jc = 0; jc < 4; jc++) {
            int n = n0 + tx + jc * 32;
            g_X0[d][t][r][n] = acc[jr][jc] + g_bP0[d][n];
        }
    }
}

// ---------------- layer1 input projections for word w ----------------
// grid ((w+1)*5, 16, 2), block 256.  A = Y[t] = [hsf[t], hsb_scan[w-t]]
__global__ void k_zproj(int w) {
    __shared__ float As[32 * 33];
    int bm = blockIdx.x, bn = blockIdx.y, d = blockIdx.z;
    int tid = threadIdx.x;
    int m0 = bm * 32;
    int t = m0 / Rd;          // tile-constant (32 | 160)
    int r0 = m0 % Rd;
    int tb = w - t;
    int tx = tid & 31, ty = tid >> 5;
    float acc[4][4];
#pragma unroll
    for (int a = 0; a < 4; a++)
#pragma unroll
        for (int c = 0; c < 4; c++) acc[a][c] = 0.f;
    int n0 = bn * 128;
    const float* Bp = &g_WihP1[d][0][0];
    for (int kb = 0; kb < 2 * Hd; kb += 32) {
        __syncthreads();
        for (int e = tid; e < 1024; e += 256) {
            int lr = e >> 5, kk = e & 31;
            int k = kb + kk;
            float v = (k < Hd) ? g_hs[0][t][r0 + lr][k]
                               : g_hs[1][tb][r0 + lr][k - Hd];
            As[lr * 33 + kk] = v;
        }
        __syncthreads();
#pragma unroll 4
        for (int kk = 0; kk < 32; kk++) {
            float av[4], bv[4];
#pragma unroll
            for (int jr = 0; jr < 4; jr++) av[jr] = As[(ty + jr * 8) * 33 + kk];
#pragma unroll
            for (int jc = 0; jc < 4; jc++)
                bv[jc] = Bp[(long)(kb + kk) * G4 + n0 + tx + jc * 32];
#pragma unroll
            for (int jr = 0; jr < 4; jr++)
#pragma unroll
                for (int jc = 0; jc < 4; jc++) acc[jr][jc] += av[jr] * bv[jc];
        }
    }
#pragma unroll
    for (int jr = 0; jr < 4; jr++) {
        int r = r0 + ty + jr * 8;
#pragma unroll
        for (int jc = 0; jc < 4; jc++) {
            int n = n0 + tx + jc * 32;
            g_Z[d][t][r][n] = acc[jr][jc] + g_bP1[d][n];
        }
    }
}

// ---------------- one LSTM recurrent step (both dirs via grid.z), fused cell ----------------
// grid (5, 32, 2), block 256. gates = Xpre + h_in @ WhhP ; update c,h.
__global__ void k_step(int l, int p, int s, int w) {
    __shared__ float As[32 * 128];
    int bm = blockIdx.x, bn = blockIdx.y, d = blockIdx.z;
    int tid = threadIdx.x;
    int r0 = bm * 32;
    const float (*hin)[Hd] = g_hbuf[p][l][d];
    float (*hout)[Hd] = g_hbuf[p ^ 1][l][d];
    float (*cst)[Hd] = g_cS[l][d];
    const float* Wp = l ? &g_WhhP1[d][0][0] : &g_WhhP0[d][0][0];
    int xidx = d ? (w - s) : s;
    const float* Xp = l ? &g_Z[d][xidx][0][0] : &g_X0[d][xidx][0][0];

    int tx = tid & 15, ty = tid >> 4;          // cols: 4 consecutive (one h-unit)
    int n0 = bn * 64 + tx * 4;
    float acc[2][4];
#pragma unroll
    for (int a = 0; a < 2; a++)
#pragma unroll
        for (int c = 0; c < 4; c++) acc[a][c] = 0.f;

    for (int kb = 0; kb < Hd; kb += 128) {
        __syncthreads();
        for (int e = tid * 4; e < 32 * 128; e += 256 * 4) {
            int lr = e >> 7, k = e & 127;
            *(float4*)&As[e] = *(const float4*)&hin[r0 + lr][kb + k];
        }
        __syncthreads();
#pragma unroll 8
        for (int kk = 0; kk < 128; kk++) {
            float4 bv = *(const float4*)&Wp[(long)(kb + kk) * G4 + n0];
            float a0 = As[ty * 128 + kk];
            float a1 = As[(ty + 16) * 128 + kk];
            acc[0][0] += a0 * bv.x; acc[0][1] += a0 * bv.y;
            acc[0][2] += a0 * bv.z; acc[0][3] += a0 * bv.w;
            acc[1][0] += a1 * bv.x; acc[1][1] += a1 * bv.y;
            acc[1][2] += a1 * bv.z; acc[1][3] += a1 * bv.w;
        }
    }
    int hh = n0 >> 2;
#pragma unroll
    for (int jr = 0; jr < 2; jr++) {
        int row = r0 + ty + jr * 16;
        float4 xr = *(const float4*)(Xp + (long)row * G4 + n0);
        float gi = acc[jr][0] + xr.x;
        float gf = acc[jr][1] + xr.y;
        float gg = acc[jr][2] + xr.z;
        float go = acc[jr][3] + xr.w;
        float si = 1.f / (1.f + expf(-gi));
        float sf = 1.f / (1.f + expf(-gf));
        float so = 1.f / (1.f + expf(-go));
        float tg = tanhf(gg);
        float c = sf * cst[row][hh] + si * tg;
        float h = so * tanhf(c);
        cst[row][hh] = c;
        hout[row][hh] = h;
        if (l == 0) g_hs[d][s][row][hh] = h;
    }
}

// ---------------- pack final layer1 states for word w: [bwd_h, fwd_h] ----------------
__global__ void k_packst(int w, int pb) {
    int i = blockIdx.x * blockDim.x + threadIdx.x;
    if (i >= Rd * 2 * Hd) return;
    int r = i / (2 * Hd), k = i % (2 * Hd);
    int nc = r >> 5, b = r & 31;
    float v = (k < Hd) ? g_hbuf[pb][1][1][r][k]       // layer1 backward final h
                       : g_hbuf[pb][1][0][r][k - Hd]; // layer1 forward final h
    g_packed[(nc * Td + w) * Bd + b][k] = v;
}

// ---------------- final vocab projection: out = packed @ Wfc.T + bfc ----------------
// grid (100, 239), block 256
__global__ void k_final(const float* __restrict__ Wfc, const float* __restrict__ bfc,
                        float* __restrict__ out) {
    __shared__ float As[32 * 33];
    __shared__ float Ws[128 * 33];
    int bm = blockIdx.x, bn = blockIdx.y;
    int tid = threadIdx.x;
    int m0 = bm * 32, n0 = bn * 128;
    int tx = tid & 31, ty = tid >> 5;
    float acc[4][4];
#pragma unroll
    for (int a = 0; a < 4; a++)
#pragma unroll
        for (int c = 0; c < 4; c++) acc[a][c] = 0.f;
    for (int kb = 0; kb < 2 * Hd; kb += 32) {
        __syncthreads();
        for (int e = tid; e < 1024; e += 256) {
            int lr = e >> 5, kk = e & 31;
            As[lr * 33 + kk] = g_packed[m0 + lr][kb + kk];
        }
        for (int e = tid; e < 4096; e += 256) {
            int nn = e >> 5, kk = e & 31;
            int n = n0 + nn;
            Ws[nn * 33 + kk] = (n < Vd) ? Wfc[(long)n * (2 * Hd) + kb + kk] : 0.f;
        }
        __syncthreads();
#pragma unroll 4
        for (int kk = 0; kk < 32; kk++) {
            float av[4], bv[4];
#pragma unroll
            for (int jr = 0; jr < 4; jr++) av[jr] = As[(ty + jr * 8) * 33 + kk];
#pragma unroll
            for (int jc = 0; jc < 4; jc++) bv[jc] = Ws[(tx + jc * 32) * 33 + kk];
#pragma unroll
            for (int jr = 0; jr < 4; jr++)
#pragma unroll
                for (int jc = 0; jc < 4; jc++) acc[jr][jc] += av[jr] * bv[jc];
        }
    }
#pragma unroll
    for (int jr = 0; jr < 4; jr++) {
        int m = m0 + ty + jr * 8;
#pragma unroll
        for (int jc = 0; jc < 4; jc++) {
            int n = n0 + tx + jc * 32;
            if (n < Vd) out[(long)m * Vd + n] = acc[jr][jc] + bfc[n];
        }
    }
}

// ---------------- host orchestration (graph-capturable: launches only) ----------------
extern "C" void kernel_launch(void* const* d_in, const int* in_sizes, int n_in,
                              void* d_out, int out_size) {
    const float* img  = (const float*)d_in[0];
    const int*   cap  = (const int*)d_in[1];
    const float* emb  = (const float*)d_in[2];
    const float* Wh   = (const float*)d_in[3];
    const float* bh   = (const float*)d_in[4];
    const float* Wc   = (const float*)d_in[5];
    const float* bc   = (const float*)d_in[6];
    const float* Wih0 = (const float*)d_in[7];
    const float* Whh0 = (const float*)d_in[8];
    const float* bih0 = (const float*)d_in[9];
    const float* bhh0 = (const float*)d_in[10];
    const float* Wih1 = (const float*)d_in[11];
    const float* Whh1 = (const float*)d_in[12];
    const float* bih1 = (const float*)d_in[13];
    const float* bhh1 = (const float*)d_in[14];
    const float* Wfc  = (const float*)d_in[15];
    const float* bfc  = (const float*)d_in[16];
    float* out = (float*)d_out;

    k_pack<<<dim3(16384, 6), 256>>>(Wih0, Whh0, bih0, bhh0, Wih1, Whh1, bih1, bhh1);
    k_init<<<(2 * Bd * Hd + 255) / 256, 256>>>(img, Wh, bh, Wc, bc);
    k_xproj<<<dim3(100, 16, 2), 256>>>(emb, cap);

    int p0 = 0, p1 = 0;
    for (int w = 0; w < Td; w++) {
        for (int s = 0; s <= w; s++) {
            k_step<<<dim3(5, 32, 2), 256>>>(0, p0, s, w);
            p0 ^= 1;
        }
        k_zproj<<<dim3((w + 1) * 5, 16, 2), 256>>>(w);
        for (int s = 0; s <= w; s++) {
            k_step<<<dim3(5, 32, 2), 256>>>(1, p1, s, w);
            p1 ^= 1;
        }
        k_packst<<<(Rd * 2 * Hd + 255) / 256, 256>>>(w, p1);
    }
    k_final<<<dim3(100, 239), 256>>>(Wfc, bfc, out);
}